// round 2
// baseline (speedup 1.0000x reference)
#include <cuda_runtime.h>
#include <math.h>

// ============================================================================
// FasterMultiHeadAttention — fp32 SIMT for GB300 (sm_103a)
//   Stage 1: QKV GEMM  [4096,1024] @ [1024,3072] + bias  -> g_qkv
//   Stage 2: Flash attention per (b,h,q-tile)            -> g_attn [BS,D]
//   Stage 3: Out GEMM  [4096,1024] @ [1024,1024] + bias  -> d_out
// R1 change: double-buffered GEMM mainloop (reg prefetch, 1 bar/iter).
// ============================================================================

constexpr int B_  = 2;
constexpr int S_  = 2048;
constexpr int D_  = 1024;
constexpr int H_  = 16;
constexpr int HD_ = 64;
constexpr int BS_ = B_ * S_;     // 4096
constexpr int D3_ = 3 * D_;      // 3072

// Scratch (device globals: allocation-guard safe)
__device__ float g_qkv[(size_t)BS_ * D3_];   // ~50 MB
__device__ float g_attn[(size_t)BS_ * D_];   // ~17 MB

// ---------------------------------------------------------------------------
// GEMM: C[M,N] = A[M,K] @ B[K,N] + bias[N]
// 128x128 tile, BK=16, 256 threads, 8x8 micro-tile, double-buffered smem.
// ---------------------------------------------------------------------------
constexpr int GBM = 128, GBN = 128, GBK = 16;

__global__ __launch_bounds__(256, 2)
void sgemm_bias(const float* __restrict__ A, const float* __restrict__ Bw,
                const float* __restrict__ bias, float* __restrict__ C,
                int M, int N, int K)
{
    __shared__ __align__(16) float As[2][GBK][GBM + 4];  // k-major, padded
    __shared__ __align__(16) float Bs[2][GBK][GBN];

    const int tid  = threadIdx.x;
    const int bcol = blockIdx.x * GBN;
    const int brow = blockIdx.y * GBM;
    const int tx   = tid & 15;    // 16 thread-cols
    const int ty   = tid >> 4;    // 16 thread-rows

    // A-tile loader coords: 2 float4 per thread (128 rows x 16 cols)
    const int ar0 = tid >> 2;            // 0..63  (then +64)
    const int ac4 = (tid & 3) << 2;      // 0,4,8,12
    // B-tile loader coords: 2 float4 per thread (16 rows x 128 cols)
    const int br0 = tid >> 5;            // 0..7   (then +8)
    const int bc4 = (tid & 31) << 2;     // 0..124

    float acc[8][8];
#pragma unroll
    for (int i = 0; i < 8; i++)
#pragma unroll
        for (int j = 0; j < 8; j++) acc[i][j] = 0.f;

    const float* Aptr = A + (size_t)brow * K;
    const float* Bptr = Bw + bcol;

    // ---- prologue: load tile 0 into buffer 0 ----
    {
        float4 a0 = *(const float4*)(Aptr + (size_t)ar0        * K + ac4);
        float4 a1 = *(const float4*)(Aptr + (size_t)(ar0 + 64) * K + ac4);
        float4 b0 = *(const float4*)(Bptr + (size_t)br0       * N + bc4);
        float4 b1 = *(const float4*)(Bptr + (size_t)(br0 + 8) * N + bc4);
        As[0][ac4 + 0][ar0] = a0.x; As[0][ac4 + 1][ar0] = a0.y;
        As[0][ac4 + 2][ar0] = a0.z; As[0][ac4 + 3][ar0] = a0.w;
        As[0][ac4 + 0][ar0 + 64] = a1.x; As[0][ac4 + 1][ar0 + 64] = a1.y;
        As[0][ac4 + 2][ar0 + 64] = a1.z; As[0][ac4 + 3][ar0 + 64] = a1.w;
        *(float4*)&Bs[0][br0][bc4]     = b0;
        *(float4*)&Bs[0][br0 + 8][bc4] = b1;
    }
    __syncthreads();

    int buf = 0;
    for (int k0 = 0; k0 < K; k0 += GBK) {
        // ---- prefetch next tile into registers (overlaps with compute) ----
        float4 pa0, pa1, pb0, pb1;
        const bool has_next = (k0 + GBK) < K;
        if (has_next) {
            int kn = k0 + GBK;
            pa0 = *(const float4*)(Aptr + (size_t)ar0        * K + kn + ac4);
            pa1 = *(const float4*)(Aptr + (size_t)(ar0 + 64) * K + kn + ac4);
            pb0 = *(const float4*)(Bptr + (size_t)(kn + br0)     * N + bc4);
            pb1 = *(const float4*)(Bptr + (size_t)(kn + br0 + 8) * N + bc4);
        }

        // ---- compute on current buffer ----
#pragma unroll
        for (int kk = 0; kk < GBK; kk++) {
            float ar[8], br[8];
            *(float4*)(ar + 0) = *(const float4*)&As[buf][kk][ty * 8 + 0];
            *(float4*)(ar + 4) = *(const float4*)&As[buf][kk][ty * 8 + 4];
            *(float4*)(br + 0) = *(const float4*)&Bs[buf][kk][tx * 8 + 0];
            *(float4*)(br + 4) = *(const float4*)&Bs[buf][kk][tx * 8 + 4];
#pragma unroll
            for (int i = 0; i < 8; i++)
#pragma unroll
                for (int j = 0; j < 8; j++)
                    acc[i][j] = fmaf(ar[i], br[j], acc[i][j]);
        }

        // ---- commit prefetched tile to the other buffer ----
        if (has_next) {
            int nb = buf ^ 1;
            As[nb][ac4 + 0][ar0] = pa0.x; As[nb][ac4 + 1][ar0] = pa0.y;
            As[nb][ac4 + 2][ar0] = pa0.z; As[nb][ac4 + 3][ar0] = pa0.w;
            As[nb][ac4 + 0][ar0 + 64] = pa1.x; As[nb][ac4 + 1][ar0 + 64] = pa1.y;
            As[nb][ac4 + 2][ar0 + 64] = pa1.z; As[nb][ac4 + 3][ar0 + 64] = pa1.w;
            *(float4*)&Bs[nb][br0][bc4]     = pb0;
            *(float4*)&Bs[nb][br0 + 8][bc4] = pb1;
            __syncthreads();
            buf = nb;
        }
    }

    // ---- epilogue: add bias, store ----
    float bv[8];
#pragma unroll
    for (int j = 0; j < 8; j++) bv[j] = bias[bcol + tx * 8 + j];

#pragma unroll
    for (int i = 0; i < 8; i++) {
        size_t roff = (size_t)(brow + ty * 8 + i) * N + bcol + tx * 8;
        float4 c0 = make_float4(acc[i][0] + bv[0], acc[i][1] + bv[1],
                                acc[i][2] + bv[2], acc[i][3] + bv[3]);
        float4 c1 = make_float4(acc[i][4] + bv[4], acc[i][5] + bv[5],
                                acc[i][6] + bv[6], acc[i][7] + bv[7]);
        *(float4*)(C + roff)     = c0;
        *(float4*)(C + roff + 4) = c1;
    }
}

// ---------------------------------------------------------------------------
// Flash attention: one block per (q-tile of 64, head, batch). 256 threads.
// Thread (row = tid/4, quad = tid%4): quad owns 8 keys for scores and a
// 16-wide d-slice for the PV accumulation. Online softmax.
// ---------------------------------------------------------------------------
constexpr int BQ   = 64;
constexpr int BKV  = 32;
constexpr int KSTR = HD_ + 4;    // 68 floats (272B, 16B-aligned rows)
constexpr int PSTR = BKV + 4;    // 36

__global__ __launch_bounds__(256, 2)
void attn_kernel(const float* __restrict__ qkv, float* __restrict__ outp)
{
    __shared__ __align__(16) float Qs[BQ][KSTR];
    __shared__ __align__(16) float Ks[BKV][KSTR];
    __shared__ __align__(16) float Vs[BKV][KSTR];
    __shared__ float Ps[BQ][PSTR];

    const int tid  = threadIdx.x;
    const int row  = tid >> 2;     // 0..63
    const int quad = tid & 3;      // 0..3
    const int b  = blockIdx.z;
    const int h  = blockIdx.y;
    const int q0 = blockIdx.x * BQ;

    const float* qbase = qkv + ((size_t)(b * S_ + q0)) * D3_ + h * HD_;
    const float* kbase = qkv + ((size_t)(b * S_)) * D3_ + D_      + h * HD_;
    const float* vbase = qkv + ((size_t)(b * S_)) * D3_ + 2 * D_  + h * HD_;

    // ---- load Q tile: 64x64 = 1024 float4, 4 per thread ----
#pragma unroll
    for (int it = 0; it < 4; it++) {
        int id = tid + it * 256;
        int r  = id >> 4;
        int c4 = (id & 15) << 2;
        *(float4*)&Qs[r][c4] = *(const float4*)(qbase + (size_t)r * D3_ + c4);
    }
    __syncthreads();

    // cache this thread's Q row in registers (16 float4 = 64 regs)
    float4 qr[16];
#pragma unroll
    for (int kk = 0; kk < 16; kk++)
        qr[kk] = *(const float4*)&Qs[row][kk << 2];

    float4 o0 = {0,0,0,0}, o1 = {0,0,0,0}, o2 = {0,0,0,0}, o3 = {0,0,0,0};
    float m_run = -1e30f, l_run = 0.f;

    for (int kv0 = 0; kv0 < S_; kv0 += BKV) {
        __syncthreads();   // prior iter's Ks/Vs reads complete before refill

        // ---- load K,V tiles: 32x64 each = 512 float4, 2 per thread ----
#pragma unroll
        for (int it = 0; it < 2; it++) {
            int id = tid + it * 256;
            int r  = id >> 4;
            int c4 = (id & 15) << 2;
            *(float4*)&Ks[r][c4] =
                *(const float4*)(kbase + (size_t)(kv0 + r) * D3_ + c4);
            *(float4*)&Vs[r][c4] =
                *(const float4*)(vbase + (size_t)(kv0 + r) * D3_ + c4);
        }
        __syncthreads();

        // ---- scores: s[j] = (q . k_j) * 1/8, j in quad's 8-slice ----
        // stagger jj by quad -> K-row banks 4j mod 32 distinct per quad
        float s[8];
#pragma unroll
        for (int jj = 0; jj < 8; jj++) {
            int jj2 = (jj + quad) & 7;
            int j   = (quad << 3) + jj2;
            float4 a = {0,0,0,0};
#pragma unroll
            for (int kk = 0; kk < 16; kk++) {
                float4 k4 = *(const float4*)&Ks[j][kk << 2];
                a.x = fmaf(qr[kk].x, k4.x, a.x);
                a.y = fmaf(qr[kk].y, k4.y, a.y);
                a.z = fmaf(qr[kk].z, k4.z, a.z);
                a.w = fmaf(qr[kk].w, k4.w, a.w);
            }
            s[jj2] = (a.x + a.y + a.z + a.w) * 0.125f;
        }

        // ---- online softmax update (reduce across the 4 quad lanes) ----
        float m_t = s[0];
#pragma unroll
        for (int jj = 1; jj < 8; jj++) m_t = fmaxf(m_t, s[jj]);
        m_t = fmaxf(m_t, __shfl_xor_sync(0xffffffffu, m_t, 1));
        m_t = fmaxf(m_t, __shfl_xor_sync(0xffffffffu, m_t, 2));

        float m_new = fmaxf(m_run, m_t);
        float corr  = __expf(m_run - m_new);

        float l_t = 0.f;
#pragma unroll
        for (int jj = 0; jj < 8; jj++) {
            float p = __expf(s[jj] - m_new);
            l_t += p;
            Ps[row][(quad << 3) + jj] = p;
        }
        l_t += __shfl_xor_sync(0xffffffffu, l_t, 1);
        l_t += __shfl_xor_sync(0xffffffffu, l_t, 2);
        l_run = l_run * corr + l_t;
        m_run = m_new;

        o0.x *= corr; o0.y *= corr; o0.z *= corr; o0.w *= corr;
        o1.x *= corr; o1.y *= corr; o1.z *= corr; o1.w *= corr;
        o2.x *= corr; o2.y *= corr; o2.z *= corr; o2.w *= corr;
        o3.x *= corr; o3.y *= corr; o3.z *= corr; o3.w *= corr;

        __syncwarp();   // Ps written/read within the same 4-lane group's warp

        // ---- PV: O[row, quad*16 .. +15] += sum_j p_j * V[j, :] ----
        // stagger j by quad -> V banks (4js + 20q) mod 32 distinct per quad
#pragma unroll
        for (int js = 0; js < BKV; js++) {
            int j   = (js + quad) & 31;
            float p = Ps[row][j];
            const float* vr = &Vs[j][quad << 4];
            float4 v0 = *(const float4*)(vr + 0);
            float4 v1 = *(const float4*)(vr + 4);
            float4 v2 = *(const float4*)(vr + 8);
            float4 v3 = *(const float4*)(vr + 12);
            o0.x = fmaf(p, v0.x, o0.x); o0.y = fmaf(p, v0.y, o0.y);
            o0.z = fmaf(p, v0.z, o0.z); o0.w = fmaf(p, v0.w, o0.w);
            o1.x = fmaf(p, v1.x, o1.x); o1.y = fmaf(p, v1.y, o1.y);
            o1.z = fmaf(p, v1.z, o1.z); o1.w = fmaf(p, v1.w, o1.w);
            o2.x = fmaf(p, v2.x, o2.x); o2.y = fmaf(p, v2.y, o2.y);
            o2.z = fmaf(p, v2.z, o2.z); o2.w = fmaf(p, v2.w, o2.w);
            o3.x = fmaf(p, v3.x, o3.x); o3.y = fmaf(p, v3.y, o3.y);
            o3.z = fmaf(p, v3.z, o3.z); o3.w = fmaf(p, v3.w, o3.w);
        }
    }

    // ---- normalize and write to g_attn as [B*S, D] ----
    float inv = 1.f / l_run;
    o0.x *= inv; o0.y *= inv; o0.z *= inv; o0.w *= inv;
    o1.x *= inv; o1.y *= inv; o1.z *= inv; o1.w *= inv;
    o2.x *= inv; o2.y *= inv; o2.z *= inv; o2.w *= inv;
    o3.x *= inv; o3.y *= inv; o3.z *= inv; o3.w *= inv;

    float* ob = outp + ((size_t)(b * S_ + q0 + row)) * D_ + h * HD_ + (quad << 4);
    *(float4*)(ob + 0)  = o0;
    *(float4*)(ob + 4)  = o1;
    *(float4*)(ob + 8)  = o2;
    *(float4*)(ob + 12) = o3;
}

// ---------------------------------------------------------------------------
// Launch
// ---------------------------------------------------------------------------
extern "C" void kernel_launch(void* const* d_in, const int* in_sizes, int n_in,
                              void* d_out, int out_size)
{
    const float* x    = (const float*)d_in[0];
    const float* Wqkv = (const float*)d_in[1];
    const float* bqkv = (const float*)d_in[2];
    const float* Wout = (const float*)d_in[3];
    const float* bout = (const float*)d_in[4];
    float* out = (float*)d_out;

    float *qkv, *attn;
    cudaGetSymbolAddress((void**)&qkv,  g_qkv);
    cudaGetSymbolAddress((void**)&attn, g_attn);

    dim3 blk(256);
    // Stage 1: QKV projection
    sgemm_bias<<<dim3(D3_ / GBN, BS_ / GBM), blk>>>(x, Wqkv, bqkv, qkv,
                                                    BS_, D3_, D_);
    // Stage 2: attention
    attn_kernel<<<dim3(S_ / BQ, H_, B_), blk>>>(qkv, attn);
    // Stage 3: output projection
    sgemm_bias<<<dim3(D_ / GBN, BS_ / GBM), blk>>>(attn, Wout, bout, out,
                                                   BS_, D_, D_);
}

// round 5
// speedup vs baseline: 2.8604x; 2.8604x over previous
#include <cuda_runtime.h>
#include <math.h>
#include <stdint.h>

// ============================================================================
// FasterMultiHeadAttention — GB300 (sm_103a)
//   Stage 1: QKV GEMM  fp32 SIMT (double-buffered)        -> g_qkv
//   Stage 2: Flash attention, tf32 mma.sync.m16n8k8       -> g_attn
//   Stage 3: Out GEMM  fp32 SIMT                          -> d_out
// R5: resubmit of R4 (broker flakes; kernel has never run). Single-variable
//     experiment vs the 3052us R2 baseline: tensorized attention only.
// ============================================================================

constexpr int B_  = 2;
constexpr int S_  = 2048;
constexpr int D_  = 1024;
constexpr int H_  = 16;
constexpr int HD_ = 64;
constexpr int BS_ = B_ * S_;     // 4096
constexpr int D3_ = 3 * D_;      // 3072

__device__ float g_qkv[(size_t)BS_ * D3_];   // ~50 MB
__device__ float g_attn[(size_t)BS_ * D_];   // ~17 MB

// ---------------------------------------------------------------------------
// fp32 GEMM: C = A @ B + bias, 128x128x16, double-buffered (R2-proven)
// ---------------------------------------------------------------------------
constexpr int GBM = 128, GBN = 128, GBK = 16;

__global__ __launch_bounds__(256, 2)
void sgemm_bias(const float* __restrict__ A, const float* __restrict__ Bw,
                const float* __restrict__ bias, float* __restrict__ C,
                int M, int N, int K)
{
    __shared__ __align__(16) float As[2][GBK][GBM + 4];
    __shared__ __align__(16) float Bs[2][GBK][GBN];

    const int tid  = threadIdx.x;
    const int bcol = blockIdx.x * GBN;
    const int brow = blockIdx.y * GBM;
    const int tx   = tid & 15;
    const int ty   = tid >> 4;

    const int ar0 = tid >> 2;
    const int ac4 = (tid & 3) << 2;
    const int br0 = tid >> 5;
    const int bc4 = (tid & 31) << 2;

    float acc[8][8];
#pragma unroll
    for (int i = 0; i < 8; i++)
#pragma unroll
        for (int j = 0; j < 8; j++) acc[i][j] = 0.f;

    const float* Aptr = A + (size_t)brow * K;
    const float* Bptr = Bw + bcol;

    {
        float4 a0 = *(const float4*)(Aptr + (size_t)ar0        * K + ac4);
        float4 a1 = *(const float4*)(Aptr + (size_t)(ar0 + 64) * K + ac4);
        float4 b0 = *(const float4*)(Bptr + (size_t)br0       * N + bc4);
        float4 b1 = *(const float4*)(Bptr + (size_t)(br0 + 8) * N + bc4);
        As[0][ac4 + 0][ar0] = a0.x; As[0][ac4 + 1][ar0] = a0.y;
        As[0][ac4 + 2][ar0] = a0.z; As[0][ac4 + 3][ar0] = a0.w;
        As[0][ac4 + 0][ar0 + 64] = a1.x; As[0][ac4 + 1][ar0 + 64] = a1.y;
        As[0][ac4 + 2][ar0 + 64] = a1.z; As[0][ac4 + 3][ar0 + 64] = a1.w;
        *(float4*)&Bs[0][br0][bc4]     = b0;
        *(float4*)&Bs[0][br0 + 8][bc4] = b1;
    }
    __syncthreads();

    int buf = 0;
    for (int k0 = 0; k0 < K; k0 += GBK) {
        float4 pa0, pa1, pb0, pb1;
        const bool has_next = (k0 + GBK) < K;
        if (has_next) {
            int kn = k0 + GBK;
            pa0 = *(const float4*)(Aptr + (size_t)ar0        * K + kn + ac4);
            pa1 = *(const float4*)(Aptr + (size_t)(ar0 + 64) * K + kn + ac4);
            pb0 = *(const float4*)(Bptr + (size_t)(kn + br0)     * N + bc4);
            pb1 = *(const float4*)(Bptr + (size_t)(kn + br0 + 8) * N + bc4);
        }

#pragma unroll
        for (int kk = 0; kk < GBK; kk++) {
            float ar[8], br[8];
            *(float4*)(ar + 0) = *(const float4*)&As[buf][kk][ty * 8 + 0];
            *(float4*)(ar + 4) = *(const float4*)&As[buf][kk][ty * 8 + 4];
            *(float4*)(br + 0) = *(const float4*)&Bs[buf][kk][tx * 8 + 0];
            *(float4*)(br + 4) = *(const float4*)&Bs[buf][kk][tx * 8 + 4];
#pragma unroll
            for (int i = 0; i < 8; i++)
#pragma unroll
                for (int j = 0; j < 8; j++)
                    acc[i][j] = fmaf(ar[i], br[j], acc[i][j]);
        }

        if (has_next) {
            int nb = buf ^ 1;
            As[nb][ac4 + 0][ar0] = pa0.x; As[nb][ac4 + 1][ar0] = pa0.y;
            As[nb][ac4 + 2][ar0] = pa0.z; As[nb][ac4 + 3][ar0] = pa0.w;
            As[nb][ac4 + 0][ar0 + 64] = pa1.x; As[nb][ac4 + 1][ar0 + 64] = pa1.y;
            As[nb][ac4 + 2][ar0 + 64] = pa1.z; As[nb][ac4 + 3][ar0 + 64] = pa1.w;
            *(float4*)&Bs[nb][br0][bc4]     = pb0;
            *(float4*)&Bs[nb][br0 + 8][bc4] = pb1;
            __syncthreads();
            buf = nb;
        }
    }

    float bv[8];
#pragma unroll
    for (int j = 0; j < 8; j++) bv[j] = bias[bcol + tx * 8 + j];

#pragma unroll
    for (int i = 0; i < 8; i++) {
        size_t roff = (size_t)(brow + ty * 8 + i) * N + bcol + tx * 8;
        float4 c0 = make_float4(acc[i][0] + bv[0], acc[i][1] + bv[1],
                                acc[i][2] + bv[2], acc[i][3] + bv[3]);
        float4 c1 = make_float4(acc[i][4] + bv[4], acc[i][5] + bv[5],
                                acc[i][6] + bv[6], acc[i][7] + bv[7]);
        *(float4*)(C + roff)     = c0;
        *(float4*)(C + roff + 4) = c1;
    }
}

// ---------------------------------------------------------------------------
// tf32 helpers
// ---------------------------------------------------------------------------
__device__ __forceinline__ uint32_t f2tf32(float f) {
    uint32_t u;
    asm("cvt.rna.tf32.f32 %0, %1;" : "=r"(u) : "f"(f));
    return u;
}

__device__ __forceinline__ void mma_tf32(float (&d)[4],
                                         const uint32_t (&a)[4],
                                         const uint32_t b0, const uint32_t b1) {
    asm volatile(
        "mma.sync.aligned.m16n8k8.row.col.f32.tf32.tf32.f32 "
        "{%0,%1,%2,%3}, {%4,%5,%6,%7}, {%8,%9}, {%0,%1,%2,%3};\n"
        : "+f"(d[0]), "+f"(d[1]), "+f"(d[2]), "+f"(d[3])
        : "r"(a[0]), "r"(a[1]), "r"(a[2]), "r"(a[3]), "r"(b0), "r"(b1));
}

// ---------------------------------------------------------------------------
// Flash attention with tf32 mma. 128 threads (4 warps), warp = 16 q-rows.
// BQ=64, BKV=64, HD=64. P overlays Ks (sync-guarded). Softmax fp32 in regs.
// Bank audit (lane g=lane>>2, c=lane&3):
//   K score reads  (stride 68): bank 4g+c        -> 32 distinct, N=1
//   P A-frag reads (stride 68): bank 4g+c        -> N=1
//   V PV reads     (stride 72): bank 8c+g (+8kc) -> 32 distinct, N=1
// ---------------------------------------------------------------------------
constexpr int ABQ   = 64;
constexpr int ABKV  = 64;
constexpr int KSTRD = 68;   // 68 mod 32 = 4
constexpr int VSTRD = 72;   // 72 mod 32 = 8

__global__ __launch_bounds__(128, 3)
void attn_mma_kernel(const float* __restrict__ qkv, float* __restrict__ outp)
{
    __shared__ __align__(16) float Ks[ABKV][KSTRD];   // K tile; Q staging; P
    __shared__ __align__(16) float Vs[ABKV][VSTRD];

    const int tid  = threadIdx.x;
    const int warp = tid >> 5;
    const int lane = tid & 31;
    const int g    = lane >> 2;
    const int c    = lane & 3;
    const int b    = blockIdx.z;
    const int h    = blockIdx.y;
    const int q0   = blockIdx.x * ABQ;

    const float* qbase = qkv + ((size_t)(b * S_ + q0)) * D3_ + h * HD_;
    const float* kbase = qkv + ((size_t)(b * S_)) * D3_ + D_     + h * HD_;
    const float* vbase = qkv + ((size_t)(b * S_)) * D3_ + 2 * D_ + h * HD_;

    // ---- stage Q tile through Ks, then pull A-fragments (pre-scaled 1/8) ----
#pragma unroll
    for (int it = 0; it < 8; it++) {
        int id = tid + it * 128;
        int r  = id >> 4;
        int c4 = (id & 15) << 2;
        *(float4*)&Ks[r][c4] = *(const float4*)(qbase + (size_t)r * D3_ + c4);
    }
    __syncthreads();

    uint32_t qa[8][4];
    {
        const int qr = warp * 16 + g;
#pragma unroll
        for (int kc = 0; kc < 8; kc++) {
            qa[kc][0] = f2tf32(0.125f * Ks[qr    ][kc * 8 + c    ]);
            qa[kc][1] = f2tf32(0.125f * Ks[qr + 8][kc * 8 + c    ]);
            qa[kc][2] = f2tf32(0.125f * Ks[qr    ][kc * 8 + c + 4]);
            qa[kc][3] = f2tf32(0.125f * Ks[qr + 8][kc * 8 + c + 4]);
        }
    }

    float o[8][4];
#pragma unroll
    for (int nt = 0; nt < 8; nt++)
#pragma unroll
        for (int i = 0; i < 4; i++) o[nt][i] = 0.f;

    float m0 = -1e30f, m1 = -1e30f, l0 = 0.f, l1 = 0.f;
    float* Pw = &Ks[warp * 16][0];   // per-warp 16x64 P region (overlays Ks)

    for (int kv0 = 0; kv0 < S_; kv0 += ABKV) {
        __syncthreads();   // prior iter's P/V reads (and Q-frag reads) done

        // ---- load K,V tiles, rounding to tf32 at store ----
#pragma unroll
        for (int it = 0; it < 8; it++) {
            int id = tid + it * 128;
            int r  = id >> 4;
            int c4 = (id & 15) << 2;
            float4 k4 = *(const float4*)(kbase + (size_t)(kv0 + r) * D3_ + c4);
            float4 v4 = *(const float4*)(vbase + (size_t)(kv0 + r) * D3_ + c4);
            uint4 ku = make_uint4(f2tf32(k4.x), f2tf32(k4.y), f2tf32(k4.z), f2tf32(k4.w));
            uint4 vu = make_uint4(f2tf32(v4.x), f2tf32(v4.y), f2tf32(v4.z), f2tf32(v4.w));
            *(uint4*)&Ks[r][c4] = ku;
            *(uint4*)&Vs[r][c4] = vu;
        }
        __syncthreads();

        // ---- scores S = (Q/8) @ K^T : 8 n-tiles x 8 k-chunks ----
        float s[8][4];
#pragma unroll
        for (int nt = 0; nt < 8; nt++) {
            s[nt][0] = s[nt][1] = s[nt][2] = s[nt][3] = 0.f;
#pragma unroll
            for (int kc = 0; kc < 8; kc++) {
                uint32_t b0 = __float_as_uint(Ks[g + 8 * nt][kc * 8 + c    ]);
                uint32_t b1 = __float_as_uint(Ks[g + 8 * nt][kc * 8 + c + 4]);
                mma_tf32(s[nt], qa[kc], b0, b1);
            }
        }

        // ---- online softmax (rows g and g+8), quad-lane reductions ----
        float mt0 = s[0][0], mt1 = s[0][2];
#pragma unroll
        for (int nt = 0; nt < 8; nt++) {
            mt0 = fmaxf(mt0, fmaxf(s[nt][0], s[nt][1]));
            mt1 = fmaxf(mt1, fmaxf(s[nt][2], s[nt][3]));
        }
        mt0 = fmaxf(mt0, __shfl_xor_sync(0xffffffffu, mt0, 1));
        mt0 = fmaxf(mt0, __shfl_xor_sync(0xffffffffu, mt0, 2));
        mt1 = fmaxf(mt1, __shfl_xor_sync(0xffffffffu, mt1, 1));
        mt1 = fmaxf(mt1, __shfl_xor_sync(0xffffffffu, mt1, 2));

        float mn0 = fmaxf(m0, mt0);
        float mn1 = fmaxf(m1, mt1);
        float corr0 = __expf(m0 - mn0);
        float corr1 = __expf(m1 - mn1);

        float ls0 = 0.f, ls1 = 0.f;
#pragma unroll
        for (int nt = 0; nt < 8; nt++) {
            s[nt][0] = __expf(s[nt][0] - mn0);
            s[nt][1] = __expf(s[nt][1] - mn0);
            s[nt][2] = __expf(s[nt][2] - mn1);
            s[nt][3] = __expf(s[nt][3] - mn1);
            ls0 += s[nt][0] + s[nt][1];
            ls1 += s[nt][2] + s[nt][3];
        }
        ls0 += __shfl_xor_sync(0xffffffffu, ls0, 1);
        ls0 += __shfl_xor_sync(0xffffffffu, ls0, 2);
        ls1 += __shfl_xor_sync(0xffffffffu, ls1, 1);
        ls1 += __shfl_xor_sync(0xffffffffu, ls1, 2);
        l0 = l0 * corr0 + ls0;  m0 = mn0;
        l1 = l1 * corr1 + ls1;  m1 = mn1;

#pragma unroll
        for (int nt = 0; nt < 8; nt++) {
            o[nt][0] *= corr0; o[nt][1] *= corr0;
            o[nt][2] *= corr1; o[nt][3] *= corr1;
        }

        // ---- write P (C-layout -> smem, tf32-rounded); overlays Ks ----
        __syncthreads();   // all warps done reading K data
#pragma unroll
        for (int nt = 0; nt < 8; nt++) {
            *(float2*)&Pw[(size_t)g * KSTRD + 8 * nt + 2 * c] =
                make_float2(__uint_as_float(f2tf32(s[nt][0])),
                            __uint_as_float(f2tf32(s[nt][1])));
            *(float2*)&Pw[(size_t)(g + 8) * KSTRD + 8 * nt + 2 * c] =
                make_float2(__uint_as_float(f2tf32(s[nt][2])),
                            __uint_as_float(f2tf32(s[nt][3])));
        }
        __syncwarp();      // P region is warp-private

        // ---- O += P @ V : 8 kv-chunks x 8 d-tiles ----
#pragma unroll
        for (int kc = 0; kc < 8; kc++) {
            uint32_t pa[4];
            pa[0] = __float_as_uint(Pw[(size_t)g       * KSTRD + 8 * kc + c    ]);
            pa[1] = __float_as_uint(Pw[(size_t)(g + 8) * KSTRD + 8 * kc + c    ]);
            pa[2] = __float_as_uint(Pw[(size_t)g       * KSTRD + 8 * kc + c + 4]);
            pa[3] = __float_as_uint(Pw[(size_t)(g + 8) * KSTRD + 8 * kc + c + 4]);
#pragma unroll
            for (int nt = 0; nt < 8; nt++) {
                uint32_t b0 = __float_as_uint(Vs[8 * kc + c    ][8 * nt + g]);
                uint32_t b1 = __float_as_uint(Vs[8 * kc + c + 4][8 * nt + g]);
                mma_tf32(o[nt], pa, b0, b1);
            }
        }
    }

    // ---- normalize, store to g_attn [B*S, D] ----
    float inv0 = 1.f / l0;
    float inv1 = 1.f / l1;
    const int qr = q0 + warp * 16 + g;
    float* ob0 = outp + (size_t)(b * S_ + qr)     * D_ + h * HD_;
    float* ob1 = outp + (size_t)(b * S_ + qr + 8) * D_ + h * HD_;
#pragma unroll
    for (int nt = 0; nt < 8; nt++) {
        *(float2*)&ob0[8 * nt + 2 * c] = make_float2(o[nt][0] * inv0, o[nt][1] * inv0);
        *(float2*)&ob1[8 * nt + 2 * c] = make_float2(o[nt][2] * inv1, o[nt][3] * inv1);
    }
}

// ---------------------------------------------------------------------------
// Launch
// ---------------------------------------------------------------------------
extern "C" void kernel_launch(void* const* d_in, const int* in_sizes, int n_in,
                              void* d_out, int out_size)
{
    const float* x    = (const float*)d_in[0];
    const float* Wqkv = (const float*)d_in[1];
    const float* bqkv = (const float*)d_in[2];
    const float* Wout = (const float*)d_in[3];
    const float* bout = (const float*)d_in[4];
    float* out = (float*)d_out;

    float *qkv, *attn;
    cudaGetSymbolAddress((void**)&qkv,  g_qkv);
    cudaGetSymbolAddress((void**)&attn, g_attn);

    // Stage 1: QKV projection (fp32)
    sgemm_bias<<<dim3(D3_ / GBN, BS_ / GBM), 256>>>(x, Wqkv, bqkv, qkv,
                                                    BS_, D3_, D_);
    // Stage 2: attention (tf32 tensor cores)
    attn_mma_kernel<<<dim3(S_ / ABQ, H_, B_), 128>>>(qkv, attn);
    // Stage 3: output projection (fp32)
    sgemm_bias<<<dim3(D_ / GBN, BS_ / GBM), 256>>>(attn, Wout, bout, out,
                                                   BS_, D_, D_);
}